// round 1
// baseline (speedup 1.0000x reference)
#include <cuda_runtime.h>

#define NUMN 32
#define LW   128
#define DD   256
#define HDIM 256
#define BAG  300
#define POOL 1200

// Scratch: h0 = relu-input left side (+b1 folded), h1 = right side.
__device__ float g_h0[NUMN * LW * HDIM];
__device__ float g_h1[NUMN * LW * HDIM];

// ---------------------------------------------------------------------------
// Kernel 1: gathered GEMM.  H[r,:] = fea[srow(r), :] @ W1 (+ b1 on side 0)
// rows = 32*128 = 4096 per side; tile 64x64, 256 threads, 4x4 microtile.
// grid (4 colblk, 64 rowblk, 2 side)
// ---------------------------------------------------------------------------
__global__ __launch_bounds__(256) void k_gemm(
    const float* __restrict__ fea,
    const int*   __restrict__ ind0,
    const int*   __restrict__ ind1,
    const float* __restrict__ W1a,
    const float* __restrict__ W1b,
    const float* __restrict__ b1)
{
    __shared__ float As[16][64];
    __shared__ float Bs[16][64];
    __shared__ int   srow[64];

    const int side = blockIdx.z;
    const int by   = blockIdx.y;
    const int bx   = blockIdx.x;
    const int t    = threadIdx.x;

    const int*   ind = side ? ind1 : ind0;
    const float* W   = side ? W1b  : W1a;

    if (t < 64) {
        int r   = by * 64 + t;
        int n   = r >> 7;
        int a   = r & 127;
        int pos = ind[n * LW + a] + BAG * (a & 3);
        srow[t] = ((n * 2 + side) * POOL + pos) * DD;
    }
    __syncthreads();

    float acc[4][4] = {};
    const int ty = t >> 4, tx = t & 15;

    for (int k0 = 0; k0 < DD; k0 += 16) {
        // A tile: 64 rows x 16 k  (one float4 per thread)
        {
            int ar = t >> 2, kv = (t & 3) * 4;
            float4 v = *(const float4*)(fea + srow[ar] + k0 + kv);
            As[kv + 0][ar] = v.x;
            As[kv + 1][ar] = v.y;
            As[kv + 2][ar] = v.z;
            As[kv + 3][ar] = v.w;
        }
        // B tile: 16 k x 64 cols
        {
            int kk = t >> 4, nv = (t & 15) * 4;
            *(float4*)&Bs[kk][nv] =
                *(const float4*)(W + (k0 + kk) * HDIM + bx * 64 + nv);
        }
        __syncthreads();

        #pragma unroll
        for (int kk = 0; kk < 16; kk++) {
            float4 av = *(float4*)&As[kk][ty * 4];
            float4 bv = *(float4*)&Bs[kk][tx * 4];
            float aa[4] = {av.x, av.y, av.z, av.w};
            float bb[4] = {bv.x, bv.y, bv.z, bv.w};
            #pragma unroll
            for (int i = 0; i < 4; i++)
                #pragma unroll
                for (int j = 0; j < 4; j++)
                    acc[i][j] += aa[i] * bb[j];
        }
        __syncthreads();
    }

    float* out = side ? g_h1 : g_h0;
    const int col = bx * 64 + tx * 4;
    float4 bias = make_float4(0.f, 0.f, 0.f, 0.f);
    if (!side) bias = *(const float4*)(b1 + col);

    #pragma unroll
    for (int i = 0; i < 4; i++) {
        int r = by * 64 + ty * 4 + i;
        float4 v = make_float4(acc[i][0] + bias.x, acc[i][1] + bias.y,
                               acc[i][2] + bias.z, acc[i][3] + bias.w);
        *(float4*)(out + r * HDIM + col) = v;
    }
}

// ---------------------------------------------------------------------------
// Kernel 2: scores[n, pa, pb] = sum_{a in patch pa, b in patch pb}
//              ( sum_h relu(h0[n,a,h] + h1[n,b,h]) * w2[h] )  + 16*b2
// Tile 32a x 32b per block, h chunked by 64.  Y stored transposed in SMEM
// (stride 34) so the b-fragment read is a conflict-free float2 LDS.
// grid (4 bt, 4 at, 32 n), 256 threads, 2x2 pairs/thread.
// Patch reduce: warp w holds a in [4w,4w+4); shfl_xor 16 then 1.
// ---------------------------------------------------------------------------
__global__ __launch_bounds__(256) void k_pair(
    const float* __restrict__ W2,
    const float* __restrict__ b2,
    float*       __restrict__ outs)
{
    __shared__ float X[32][64];
    __shared__ float Yt[64][34];
    __shared__ float w2s[HDIM];

    const int n  = blockIdx.z;
    const int at = blockIdx.y;
    const int bt = blockIdx.x;
    const int t  = threadIdx.x;

    w2s[t] = W2[t];

    float acc00 = 0.f, acc01 = 0.f, acc10 = 0.f, acc11 = 0.f;
    const int ty = t >> 4, tx = t & 15;
    const int a0 = ty * 2, b0 = tx * 2;

    const float* x_g = g_h0 + (n * LW + at * 32) * HDIM;
    const float* y_g = g_h1 + (n * LW + bt * 32) * HDIM;

    for (int hc = 0; hc < 4; hc++) {
        __syncthreads();   // protect prior-iter reads before overwrite
        {
            int r = t >> 3, c = (t & 7) * 8;
            const float* xp = x_g + r * HDIM + hc * 64 + c;
            const float* yp = y_g + r * HDIM + hc * 64 + c;
            float4 v0 = *(const float4*)(xp);
            float4 v1 = *(const float4*)(xp + 4);
            *(float4*)&X[r][c]     = v0;
            *(float4*)&X[r][c + 4] = v1;
            float4 w0 = *(const float4*)(yp);
            float4 w1 = *(const float4*)(yp + 4);
            Yt[c + 0][r] = w0.x; Yt[c + 1][r] = w0.y;
            Yt[c + 2][r] = w0.z; Yt[c + 3][r] = w0.w;
            Yt[c + 4][r] = w1.x; Yt[c + 5][r] = w1.y;
            Yt[c + 6][r] = w1.z; Yt[c + 7][r] = w1.w;
        }
        __syncthreads();

        const float* wp = &w2s[hc * 64];
        #pragma unroll
        for (int hh = 0; hh < 64; hh += 4) {
            float4 x0 = *(float4*)&X[a0][hh];
            float4 x1 = *(float4*)&X[a0 + 1][hh];
            float4 wv = *(const float4*)(wp + hh);
            float xa[4] = {x0.x, x0.y, x0.z, x0.w};
            float xb[4] = {x1.x, x1.y, x1.z, x1.w};
            float wf[4] = {wv.x, wv.y, wv.z, wv.w};
            #pragma unroll
            for (int u = 0; u < 4; u++) {
                float2 yv = *(float2*)&Yt[hh + u][b0];
                acc00 += fmaxf(xa[u] + yv.x, 0.f) * wf[u];
                acc01 += fmaxf(xa[u] + yv.y, 0.f) * wf[u];
                acc10 += fmaxf(xb[u] + yv.x, 0.f) * wf[u];
                acc11 += fmaxf(xb[u] + yv.y, 0.f) * wf[u];
            }
        }
    }

    // 4x4 patch reduction: each thread holds a={a0,a0+1} x b={b0,b0+1}.
    float s = acc00 + acc01 + acc10 + acc11;
    s += __shfl_xor_sync(0xffffffffu, s, 16);  // combine ty pair (a halves)
    s += __shfl_xor_sync(0xffffffffu, s, 1);   // combine tx pair (b halves)

    const int lane = t & 31, warp = t >> 5;
    if (lane < 16 && (lane & 1) == 0) {
        int pb = lane >> 1;                         // 0..7
        outs[n * 1024 + (at * 8 + warp) * 32 + bt * 8 + pb] = s + 16.0f * b2[0];
    }
}

// ---------------------------------------------------------------------------
// Kernel 3: pairs meshgrid, written as float after the 32*1024 scores.
// pairs[n, i, 0] = i/32 ; pairs[n, i, 1] = i%32
// ---------------------------------------------------------------------------
__global__ void k_pairs(float* __restrict__ outp)
{
    int idx = blockIdx.x * 256 + threadIdx.x;  // 0 .. 65535
    int i = (idx >> 1) & 1023;
    int c = idx & 1;
    outp[idx] = (float)(c ? (i & 31) : (i >> 5));
}

extern "C" void kernel_launch(void* const* d_in, const int* in_sizes, int n_in,
                              void* d_out, int out_size)
{
    // Input order: orig_fea, ind0, ind1, [k], W1a, W1b, b1, W2, b2.
    // Detect whether the python scalar `k` was materialized as a size-1 input.
    int base = 3;
    if (n_in > 3 && in_sizes[3] == 1) base = 4;

    const float* fea  = (const float*)d_in[0];
    const int*   ind0 = (const int*)d_in[1];
    const int*   ind1 = (const int*)d_in[2];
    const float* W1a  = (const float*)d_in[base + 0];
    const float* W1b  = (const float*)d_in[base + 1];
    const float* b1   = (const float*)d_in[base + 2];
    const float* W2   = (const float*)d_in[base + 3];
    const float* b2   = (const float*)d_in[base + 4];
    float* out = (float*)d_out;

    k_gemm <<<dim3(4, 64, 2), 256>>>(fea, ind0, ind1, W1a, W1b, b1);
    k_pair <<<dim3(4, 4, 32), 256>>>(W2, b2, out);
    if (out_size >= 32 * 1024 * 3)
        k_pairs<<<256, 256>>>(out + 32 * 1024);
}

// round 2
// speedup vs baseline: 1.0930x; 1.0930x over previous
#include <cuda_runtime.h>

typedef unsigned long long u64;

#define NUMN 32
#define LW   128
#define DD   256
#define HDIM 256
#define BAG  300
#define POOL 1200

// Scratch: relu-input halves (bias folded into side 0).
__device__ float g_h0[NUMN * LW * HDIM];
__device__ float g_h1[NUMN * LW * HDIM];

// ---- Blackwell packed-fp32 helpers (ptxas never emits these from C++) ----
__device__ __forceinline__ u64 f2fma(u64 a, u64 b, u64 c) {
    u64 d; asm("fma.rn.f32x2 %0,%1,%2,%3;" : "=l"(d) : "l"(a), "l"(b), "l"(c));
    return d;
}
__device__ __forceinline__ u64 f2add(u64 a, u64 b) {
    u64 d; asm("add.rn.f32x2 %0,%1,%2;" : "=l"(d) : "l"(a), "l"(b));
    return d;
}
__device__ __forceinline__ u64 f2relu(u64 a) {
    u64 d;
    asm("{\n\t.reg .f32 lo, hi;\n\t"
        "mov.b64 {lo,hi}, %1;\n\t"
        "max.f32 lo, lo, 0f00000000;\n\t"
        "max.f32 hi, hi, 0f00000000;\n\t"
        "mov.b64 %0, {lo,hi};\n\t}" : "=l"(d) : "l"(a));
    return d;
}
__device__ __forceinline__ float2 f2unpack(u64 a) {
    float2 f; asm("mov.b64 {%0,%1}, %2;" : "=f"(f.x), "=f"(f.y) : "l"(a));
    return f;
}

// ---------------------------------------------------------------------------
// Kernel 1: gathered GEMM, 128x128 tile, 8x8 microtile packed over col-pairs.
// A stored DUPLICATED in smem (Asd[k][2r]=Asd[k][2r+1]=a_r) so the FFMA2 splat
// operands {a,a} come straight out of ld.shared.v2.b64 — zero pack MOVs.
// A-reads depend only on ty (2 values/warp) -> broadcast, duplication is free.
// grid (2 colblk, 32 n, 2 side), 256 threads. Software-pipelined LDG prefetch.
// ---------------------------------------------------------------------------
__global__ __launch_bounds__(256) void k_gemm(
    const float* __restrict__ fea,
    const int*   __restrict__ ind0,
    const int*   __restrict__ ind1,
    const float* __restrict__ W1a,
    const float* __restrict__ W1b,
    const float* __restrict__ b1)
{
    __shared__ __align__(16) float Asd[16][256];
    __shared__ __align__(16) float Bs[16][128];
    __shared__ int srow[128];

    const int side = blockIdx.z, by = blockIdx.y, bx = blockIdx.x;
    const int t = threadIdx.x;
    const int* ind = side ? ind1 : ind0;
    const float* W = side ? W1b : W1a;

    if (t < 128) {
        int pos = ind[by * LW + t] + BAG * (t & 3);
        srow[t] = ((by * 2 + side) * POOL + pos) * DD;
    }

    const int ar = t >> 1, ks = (t & 1) * 8;   // A fill: row, k-offset
    const int bk = t >> 4, bc = (t & 15) * 8;  // B fill: k-row, col-offset
    const int ty = t >> 4, tx = t & 15;

    u64 acc[8][4];
    #pragma unroll
    for (int i = 0; i < 8; i++)
        #pragma unroll
        for (int j = 0; j < 4; j++) acc[i][j] = 0ull;

    __syncthreads();  // srow ready

    float4 a0, a1, w0, w1;
    {   // prefetch chunk 0
        const float* ap = fea + srow[ar] + ks;
        a0 = *(const float4*)ap; a1 = *(const float4*)(ap + 4);
        const float* wp = W + bk * HDIM + bx * 128 + bc;
        w0 = *(const float4*)wp; w1 = *(const float4*)(wp + 4);
    }

    for (int c = 0; c < 16; c++) {
        if (c) __syncthreads();  // readers of previous chunk done
        {
            float av[8] = {a0.x, a0.y, a0.z, a0.w, a1.x, a1.y, a1.z, a1.w};
            #pragma unroll
            for (int j = 0; j < 8; j++) {
                Asd[ks + j][2 * ar]     = av[j];
                Asd[ks + j][2 * ar + 1] = av[j];
            }
            *(float4*)&Bs[bk][bc]     = w0;
            *(float4*)&Bs[bk][bc + 4] = w1;
        }
        __syncthreads();

        if (c < 15) {  // prefetch next chunk while computing this one
            int k0 = (c + 1) * 16;
            const float* ap = fea + srow[ar] + k0 + ks;
            a0 = *(const float4*)ap; a1 = *(const float4*)(ap + 4);
            const float* wp = W + (k0 + bk) * HDIM + bx * 128 + bc;
            w0 = *(const float4*)wp; w1 = *(const float4*)(wp + 4);
        }

        #pragma unroll
        for (int kk = 0; kk < 16; kk++) {
            ulonglong2 al0 = *(ulonglong2*)&Asd[kk][8 * ty];        // rows 4ty+0,1
            ulonglong2 al1 = *(ulonglong2*)&Asd[kk][8 * ty + 4];    // rows 4ty+2,3
            ulonglong2 ah0 = *(ulonglong2*)&Asd[kk][128 + 8 * ty];  // rows 64+4ty+0,1
            ulonglong2 ah1 = *(ulonglong2*)&Asd[kk][128 + 8 * ty + 4];
            ulonglong2 bl  = *(ulonglong2*)&Bs[kk][tx * 4];         // col pairs
            ulonglong2 bh  = *(ulonglong2*)&Bs[kk][64 + tx * 4];
            u64 aa[8] = {al0.x, al0.y, al1.x, al1.y, ah0.x, ah0.y, ah1.x, ah1.y};
            u64 bb[4] = {bl.x, bl.y, bh.x, bh.y};
            #pragma unroll
            for (int i = 0; i < 8; i++)
                #pragma unroll
                for (int j = 0; j < 4; j++)
                    acc[i][j] = f2fma(aa[i], bb[j], acc[i][j]);
        }
    }

    float* outp = side ? g_h1 : g_h0;
    float4 bias0 = make_float4(0.f, 0.f, 0.f, 0.f), bias1 = bias0;
    if (!side) {
        bias0 = *(const float4*)(b1 + bx * 128 + tx * 4);
        bias1 = *(const float4*)(b1 + bx * 128 + 64 + tx * 4);
    }

    #pragma unroll
    for (int i = 0; i < 8; i++) {
        int arow = (i < 4) ? (ty * 4 + i) : (64 + ty * 4 + i - 4);
        float* o = outp + (by * LW + arow) * HDIM + bx * 128;
        float2 p0 = f2unpack(acc[i][0]), p1 = f2unpack(acc[i][1]);
        float2 p2 = f2unpack(acc[i][2]), p3 = f2unpack(acc[i][3]);
        *(float4*)(o + tx * 4) =
            make_float4(p0.x + bias0.x, p0.y + bias0.y, p1.x + bias0.z, p1.y + bias0.w);
        *(float4*)(o + 64 + tx * 4) =
            make_float4(p2.x + bias1.x, p2.y + bias1.y, p3.x + bias1.z, p3.y + bias1.w);
    }
}

// ---------------------------------------------------------------------------
// Kernel 2: scores = patch-sum_{4x4} sum_h relu(x[a,h]+y[b,h])*w2[h].
// 64a x 64b tile per block, 128 threads, 8a x 4b microtile, h packed in f32x2.
// b columns interleaved (tx + 16j) -> Y reads hit distinct banks; patch sums
// for b recovered with 2 shfl_xor. a rows contiguous -> patch-local in thread.
// fma pipe: ADD2+FFMA2 per output-h-pair; FMNMX relu rides the idle alu pipe.
// grid (2 bt, 2 at, 32 n).
// ---------------------------------------------------------------------------
__global__ __launch_bounds__(128) void k_pair(
    const float* __restrict__ W2,
    const float* __restrict__ b2,
    float*       __restrict__ outs)
{
    __shared__ __align__(16) float X[64][36];
    __shared__ __align__(16) float Y[64][36];
    __shared__ __align__(16) float w2s[HDIM];

    const int n = blockIdx.z, at = blockIdx.y, bt = blockIdx.x;
    const int t = threadIdx.x;
    const int ty = t >> 4, tx = t & 15;

    w2s[t]       = W2[t];
    w2s[t + 128] = W2[t + 128];

    const float* xg = g_h0 + (n * LW + at * 64) * HDIM;
    const float* yg = g_h1 + (n * LW + bt * 64) * HDIM;

    const int fr = t >> 1, fo = (t & 1) * 16;  // fill: row, h-offset

    float4 px[4], py[4];
    {   // prefetch chunk 0
        const float* xp = xg + fr * HDIM + fo;
        const float* yp = yg + fr * HDIM + fo;
        #pragma unroll
        for (int q = 0; q < 4; q++) {
            px[q] = *(const float4*)(xp + 4 * q);
            py[q] = *(const float4*)(yp + 4 * q);
        }
    }

    u64 acc[8][4];
    #pragma unroll
    for (int i = 0; i < 8; i++)
        #pragma unroll
        for (int j = 0; j < 4; j++) acc[i][j] = 0ull;

    for (int hc = 0; hc < 8; hc++) {
        if (hc) __syncthreads();
        #pragma unroll
        for (int q = 0; q < 4; q++) {
            *(float4*)&X[fr][fo + 4 * q] = px[q];
            *(float4*)&Y[fr][fo + 4 * q] = py[q];
        }
        __syncthreads();

        if (hc < 7) {
            const float* xp = xg + fr * HDIM + (hc + 1) * 32 + fo;
            const float* yp = yg + fr * HDIM + (hc + 1) * 32 + fo;
            #pragma unroll
            for (int q = 0; q < 4; q++) {
                px[q] = *(const float4*)(xp + 4 * q);
                py[q] = *(const float4*)(yp + 4 * q);
            }
        }

        #pragma unroll
        for (int hq = 0; hq < 8; hq++) {   // 4 h per quad (2 packed pairs)
            ulonglong2 wv = *(ulonglong2*)&w2s[hc * 32 + hq * 4];
            ulonglong2 xv[8];
            #pragma unroll
            for (int i = 0; i < 8; i++)
                xv[i] = *(ulonglong2*)&X[ty * 8 + i][hq * 4];
            ulonglong2 yv[4];
            #pragma unroll
            for (int j = 0; j < 4; j++)
                yv[j] = *(ulonglong2*)&Y[tx + 16 * j][hq * 4];
            #pragma unroll
            for (int i = 0; i < 8; i++)
                #pragma unroll
                for (int j = 0; j < 4; j++) {
                    acc[i][j] = f2fma(f2relu(f2add(xv[i].x, yv[j].x)), wv.x, acc[i][j]);
                    acc[i][j] = f2fma(f2relu(f2add(xv[i].y, yv[j].y)), wv.y, acc[i][j]);
                }
        }
    }

    // Patch reduction: a-patches thread-local (rows ty*8+4p+i), b-patches via
    // shuffle over the tx%4 group (b = bt*64 + tx + 16j).
    const float b2v = b2[0];
    #pragma unroll
    for (int p = 0; p < 2; p++) {
        #pragma unroll
        for (int j = 0; j < 4; j++) {
            float s = 0.f;
            #pragma unroll
            for (int i = 0; i < 4; i++) {
                float2 f = f2unpack(acc[p * 4 + i][j]);
                s += f.x + f.y;
            }
            s += __shfl_xor_sync(0xffffffffu, s, 1);
            s += __shfl_xor_sync(0xffffffffu, s, 2);
            if ((tx & 3) == 0) {
                int pa = at * 16 + ty * 2 + p;
                int pb = bt * 16 + (tx >> 2) + 4 * j;
                outs[n * 1024 + pa * 32 + pb] = s + 16.0f * b2v;
            }
        }
    }
}

// ---------------------------------------------------------------------------
// Kernel 3: pairs meshgrid after the 32*1024 scores.
// ---------------------------------------------------------------------------
__global__ void k_pairs(float* __restrict__ outp)
{
    int idx = blockIdx.x * 256 + threadIdx.x;  // 0 .. 65535
    int i = (idx >> 1) & 1023;
    int c = idx & 1;
    outp[idx] = (float)(c ? (i & 31) : (i >> 5));
}

extern "C" void kernel_launch(void* const* d_in, const int* in_sizes, int n_in,
                              void* d_out, int out_size)
{
    int base = 3;
    if (n_in > 3 && in_sizes[3] == 1) base = 4;

    const float* fea  = (const float*)d_in[0];
    const int*   ind0 = (const int*)d_in[1];
    const int*   ind1 = (const int*)d_in[2];
    const float* W1a  = (const float*)d_in[base + 0];
    const float* W1b  = (const float*)d_in[base + 1];
    const float* b1   = (const float*)d_in[base + 2];
    const float* W2   = (const float*)d_in[base + 3];
    const float* b2   = (const float*)d_in[base + 4];
    float* out = (float*)d_out;

    k_gemm <<<dim3(2, 32, 2), 256>>>(fea, ind0, ind1, W1a, W1b, b1);
    k_pair <<<dim3(2, 2, 32), 128>>>(W2, b2, out);
    if (out_size >= 32 * 1024 * 3)
        k_pairs<<<256, 256>>>(out + 32 * 1024);
}